// round 1
// baseline (speedup 1.0000x reference)
#include <cuda_runtime.h>

// Fused DepthwiseSeparableConv3d: depthwise 3x3x3 (SAME) + bias + BN + ReLU,
// then pointwise 64->128 GEMM + bias + BN + ReLU.
// B=2, D=H=W=48, C=64, F=128. fp32 throughout, packed f32x2 FMA in the GEMM.

#define NB   2
#define ND   48
#define NC   64
#define NF   128
#define WPAD 50   // padded y-row stride (even for 8B-aligned pairs, low bank conflict)

__device__ __forceinline__ unsigned long long dup2(float v) {
    unsigned long long r;
    unsigned u = __float_as_uint(v);
    asm("mov.b64 %0, {%1, %1};" : "=l"(r) : "r"(u));
    return r;
}

__device__ __forceinline__ void fma2(unsigned long long& d,
                                     unsigned long long a,
                                     unsigned long long b) {
    asm("fma.rn.f32x2 %0, %1, %2, %0;" : "+l"(d) : "l"(a), "l"(b));
}

__global__ __launch_bounds__(256, 3)
void dwsep3d_fused_kernel(
    const float* __restrict__ x,
    const float* __restrict__ dwk,   // (3,3,3,1,C)
    const float* __restrict__ dwb,   // (C)
    const float* __restrict__ g1, const float* __restrict__ b1,
    const float* __restrict__ m1, const float* __restrict__ v1,
    const float* __restrict__ pw,    // (C,F)
    const float* __restrict__ pb,    // (F)
    const float* __restrict__ g2, const float* __restrict__ b2,
    const float* __restrict__ m2, const float* __restrict__ v2,
    float* __restrict__ out)
{
    __shared__ float sW[NC * NF];      // 32768 B, pointwise weights [c][f]
    __shared__ float sY[NC * WPAD];    // 12800 B, stage-1 result transposed [c][w]
    __shared__ float sS1[NC], sT1[NC];
    __shared__ float sS2[NF], sT2[NF];

    const int tid = threadIdx.x;
    const int bid = blockIdx.x;            // 0 .. B*D*H-1
    const int h = bid % ND;
    const int d = (bid / ND) % ND;
    const int b = bid / (ND * ND);

    // ---- stage 0: stage pointwise weights + fold BN params -------------------
    {
        const float4* src = (const float4*)pw;
        float4* dst = (float4*)sW;
        #pragma unroll
        for (int i = tid; i < NC * NF / 4; i += 256) dst[i] = src[i];
    }
    if (tid < NC) {
        const int c = tid;
        float inv = g1[c] * rsqrtf(v1[c] + 1e-3f);
        sS1[c] = inv;
        sT1[c] = dwb[c] * inv + b1[c] - m1[c] * inv;   // folds dw bias + BN1
    } else if (tid < NC + NF) {
        const int f = tid - NC;
        float inv = g2[f] * rsqrtf(v2[f] + 1e-3f);
        sS2[f] = inv;
        sT2[f] = pb[f] * inv + b2[f] - m2[f] * inv;    // folds pw bias + BN2
    }
    __syncthreads();

    // ---- stage 1: depthwise 3x3x3 + BN1 + ReLU -> sY[c][w] -------------------
    {
        const int c  = tid & 63;           // channel
        const int wg = tid >> 6;           // 0..3  -> w range [wg*12, wg*12+12)
        const int w0 = wg * 12;

        float acc[12];
        #pragma unroll
        for (int j = 0; j < 12; j++) acc[j] = 0.f;

        #pragma unroll
        for (int dd = 0; dd < 3; dd++) {
            const int zd = d + dd - 1;
            if (zd < 0 || zd >= ND) continue;
            #pragma unroll
            for (int hh = 0; hh < 3; hh++) {
                const int zh = h + hh - 1;
                if (zh < 0 || zh >= ND) continue;
                const float* xb =
                    x + (((size_t)((b * ND + zd) * ND + zh)) * ND) * NC + c;
                // sliding window of 14 inputs covers 12 outputs x 3 taps
                float xv[14];
                #pragma unroll
                for (int j = 0; j < 14; j++) {
                    const int wx = w0 - 1 + j;
                    xv[j] = (wx >= 0 && wx < ND) ? __ldg(xb + wx * NC) : 0.f;
                }
                const int kb = ((dd * 3 + hh) * 3) * NC + c;
                const float k0 = __ldg(dwk + kb);
                const float k1 = __ldg(dwk + kb + NC);
                const float k2 = __ldg(dwk + kb + 2 * NC);
                #pragma unroll
                for (int j = 0; j < 12; j++)
                    acc[j] = fmaf(xv[j], k0,
                              fmaf(xv[j + 1], k1,
                               fmaf(xv[j + 2], k2, acc[j])));
            }
        }
        const float s1v = sS1[c], t1v = sT1[c];
        #pragma unroll
        for (int j = 0; j < 12; j++)
            sY[c * WPAD + w0 + j] = fmaxf(fmaf(acc[j], s1v, t1v), 0.f);
    }
    __syncthreads();

    // ---- stage 2: GEMM z[48][128] = y[48][64] @ W[64][128], packed f32x2 ----
    {
        const int fg = tid & 31;           // f tile: 4 consecutive f
        const int wg = tid >> 5;           // 0..7, 6 w's each (warp-uniform)
        const int f0 = fg * 4;
        const int w0 = wg * 6;

        unsigned long long acc[3][4];      // [w-pair][f], each = 2 fp32 (w, w+1)
        #pragma unroll
        for (int p = 0; p < 3; p++)
            #pragma unroll
            for (int q = 0; q < 4; q++) acc[p][q] = 0ull;

        #pragma unroll 8
        for (int c = 0; c < NC; c++) {
            const float4 wv = *(const float4*)&sW[c * NF + f0];
            const unsigned long long wd0 = dup2(wv.x);
            const unsigned long long wd1 = dup2(wv.y);
            const unsigned long long wd2 = dup2(wv.z);
            const unsigned long long wd3 = dup2(wv.w);
            const unsigned long long y0 =
                *(const unsigned long long*)&sY[c * WPAD + w0];
            const unsigned long long y1 =
                *(const unsigned long long*)&sY[c * WPAD + w0 + 2];
            const unsigned long long y2 =
                *(const unsigned long long*)&sY[c * WPAD + w0 + 4];
            fma2(acc[0][0], y0, wd0); fma2(acc[0][1], y0, wd1);
            fma2(acc[0][2], y0, wd2); fma2(acc[0][3], y0, wd3);
            fma2(acc[1][0], y1, wd0); fma2(acc[1][1], y1, wd1);
            fma2(acc[1][2], y1, wd2); fma2(acc[1][3], y1, wd3);
            fma2(acc[2][0], y2, wd0); fma2(acc[2][1], y2, wd1);
            fma2(acc[2][2], y2, wd2); fma2(acc[2][3], y2, wd3);
        }

        // epilogue: BN2 + ReLU, coalesced float4 stores
        const float4 s2 = *(const float4*)&sS2[f0];
        const float4 t2 = *(const float4*)&sT2[f0];
        float* ob = out + (((size_t)((b * ND + d) * ND + h)) * ND) * NF;

        #pragma unroll
        for (int p = 0; p < 3; p++) {
            float lo[4], hi[4];
            #pragma unroll
            for (int q = 0; q < 4; q++) {
                lo[q] = __uint_as_float((unsigned)(acc[p][q] & 0xffffffffull));
                hi[q] = __uint_as_float((unsigned)(acc[p][q] >> 32));
            }
            float4 o0, o1;
            o0.x = fmaxf(fmaf(lo[0], s2.x, t2.x), 0.f);
            o0.y = fmaxf(fmaf(lo[1], s2.y, t2.y), 0.f);
            o0.z = fmaxf(fmaf(lo[2], s2.z, t2.z), 0.f);
            o0.w = fmaxf(fmaf(lo[3], s2.w, t2.w), 0.f);
            o1.x = fmaxf(fmaf(hi[0], s2.x, t2.x), 0.f);
            o1.y = fmaxf(fmaf(hi[1], s2.y, t2.y), 0.f);
            o1.z = fmaxf(fmaf(hi[2], s2.z, t2.z), 0.f);
            o1.w = fmaxf(fmaf(hi[3], s2.w, t2.w), 0.f);
            *(float4*)&ob[(size_t)(w0 + 2 * p) * NF + f0]     = o0;
            *(float4*)&ob[(size_t)(w0 + 2 * p + 1) * NF + f0] = o1;
        }
    }
}

extern "C" void kernel_launch(void* const* d_in, const int* in_sizes, int n_in,
                              void* d_out, int out_size) {
    const float* x   = (const float*)d_in[0];
    const float* dwk = (const float*)d_in[1];
    const float* dwb = (const float*)d_in[2];
    const float* g1  = (const float*)d_in[3];
    const float* b1  = (const float*)d_in[4];
    const float* m1  = (const float*)d_in[5];
    const float* v1  = (const float*)d_in[6];
    const float* pw  = (const float*)d_in[7];
    const float* pb  = (const float*)d_in[8];
    const float* g2  = (const float*)d_in[9];
    const float* b2  = (const float*)d_in[10];
    const float* m2  = (const float*)d_in[11];
    const float* v2  = (const float*)d_in[12];
    float* out = (float*)d_out;

    dim3 grid(NB * ND * ND);   // 4608 blocks: one (b,d,h) row each
    dim3 block(256);
    dwsep3d_fused_kernel<<<grid, block>>>(x, dwk, dwb, g1, b1, m1, v1,
                                          pw, pb, g2, b2, m2, v2, out);
}